// round 10
// baseline (speedup 1.0000x reference)
#include <cuda_runtime.h>
#include <math.h>

#define BB 64
#define FF 512
#define EE 256
#define HH 8
#define DD 32
#define LL 4

// Partial column sums: [0]=kw [1]=vw [2]=vb [3]=qv, 16 row-slices each.
__device__ float g_part[4][16][EE];
// Per-head collapsed scalars {A0, P, R, VA, VB} (A0,P,R pre-scaled by 1/sqrt(D))
__device__ __align__(128) float g_scal[HH][8];
__device__ unsigned int g_cnt = 0;

__device__ __forceinline__ float ex2f(float x) {
    float y;
    asm("ex2.approx.ftz.f32 %0, %1;" : "=f"(y) : "f"(x));
    return y;
}

// ---------------------------------------------------------------------------
// Kernel A: grid = 48 (3 tasks x 16 row-slices), 256 threads (one per column).
//   task 0: kw += emb_w[r] * k_w[r][c]
//   task 1: vw += emb_w[r] * v_w[r][c]  AND  vb += emb_b[r] * v_w[r][c]
//   task 2: qv += emb_b[r] * q_w[r][c]
// Last-arriving block sums partials, adds biases, forms the 5 head scalars.
// ---------------------------------------------------------------------------
__global__ void __launch_bounds__(256)
precompute_kernel(const float* __restrict__ emb_w,
                  const float* __restrict__ emb_b,
                  const float* __restrict__ q_w,
                  const float* __restrict__ q_b,
                  const float* __restrict__ k_w,
                  const float* __restrict__ v_w,
                  const float* __restrict__ v_b,
                  const float* __restrict__ attn_w) {
    __shared__ unsigned int s_last;

    const int task  = blockIdx.x >> 4;    // 0,1,2
    const int slice = blockIdx.x & 15;    // row slice (16 rows)
    const int c     = threadIdx.x;        // output column 0..255
    const int r0    = slice * 16;

    if (task == 0) {
        const float* mp = k_w + r0 * EE + c;
        float acc = 0.f;
        #pragma unroll
        for (int i = 0; i < 16; i++) acc = fmaf(emb_w[r0 + i], mp[i * EE], acc);
        g_part[0][slice][c] = acc;
    } else if (task == 1) {
        const float* mp = v_w + r0 * EE + c;
        float accw = 0.f, accb = 0.f;
        #pragma unroll
        for (int i = 0; i < 16; i++) {
            float mv = mp[i * EE];
            accw = fmaf(emb_w[r0 + i], mv, accw);
            accb = fmaf(emb_b[r0 + i], mv, accb);
        }
        g_part[1][slice][c] = accw;
        g_part[2][slice][c] = accb;
    } else {
        const float* mp = q_w + r0 * EE + c;
        float acc = 0.f;
        #pragma unroll
        for (int i = 0; i < 16; i++) acc = fmaf(emb_b[r0 + i], mp[i * EE], acc);
        g_part[3][slice][c] = acc;
    }

    __threadfence();                      // release partials
    __syncthreads();
    if (c == 0) {
        unsigned int prev = atomicAdd(&g_cnt, 1u);
        s_last = (prev == 47u) ? 1u : 0u;
    }
    __syncthreads();
    if (s_last == 0u) return;

    // ---------------- finish (exactly one block reaches here) ----------------
    float kw = 0.f, vw = 0.f, vb = 0.f, qv = 0.f;
    #pragma unroll
    for (int s = 0; s < 16; s++) {
        kw += __ldcg(&g_part[0][s][c]);
        vw += __ldcg(&g_part[1][s][c]);
        vb += __ldcg(&g_part[2][s][c]);
        qv += __ldcg(&g_part[3][s][c]);
    }
    vb += v_b[c];
    qv += q_b[c];
    float aw = attn_w[c];

    const float scale = 0.17677669529663687f;   // 1/sqrt(32)
    float A0 = qv * kw, P = vw * kw, R = vb * kw, VA = vw * aw, VB = vb * aw;
    #pragma unroll
    for (int o = 16; o > 0; o >>= 1) {
        A0 += __shfl_xor_sync(0xffffffffu, A0, o);
        P  += __shfl_xor_sync(0xffffffffu, P,  o);
        R  += __shfl_xor_sync(0xffffffffu, R,  o);
        VA += __shfl_xor_sync(0xffffffffu, VA, o);
        VB += __shfl_xor_sync(0xffffffffu, VB, o);
    }
    const int lane = c & 31, h = c >> 5;
    if (lane == 0) {
        g_scal[h][0] = A0 * scale;
        g_scal[h][1] = P  * scale;
        g_scal[h][2] = R  * scale;
        g_scal[h][3] = VA;
        g_scal[h][4] = VB;
    }
    if (c == 0) g_cnt = 0u;               // reset for the next graph replay
}

// ---------------------------------------------------------------------------
// Kernel B: grid = 64 (one block per batch), 256 threads = 8 warps = 8 heads.
// NO occupancy cap (one block/SM anyway) -> ~40 regs, zero spills.
// Warp h: x via 4x LDG.128, max/min butterfly, L=4 recursion with 4-way ILP
// accumulators (each exp consumed immediately), 1x STG.128 epilogue.
// ---------------------------------------------------------------------------
__global__ void __launch_bounds__(256, 1)
attn_kernel(const float* __restrict__ features,
            const float* __restrict__ attn_b,
            float* __restrict__ out) {
    __shared__ float s_ox[HH], s_hc[HH];

    const int b    = blockIdx.x;
    const int t    = threadIdx.x;
    const int warp = t >> 5;
    const int lane = t & 31;

    // ---- all loads issued up front: 4 x LDG.128 of the feature vector ----
    const float4* xb4 = reinterpret_cast<const float4*>(features + b * FF);
    float4 v0 = xb4[lane +  0];
    float4 v1 = xb4[lane + 32];
    float4 v2 = xb4[lane + 64];
    float4 v3 = xb4[lane + 96];

    float A0 = g_scal[warp][0];
    float P  = g_scal[warp][1];
    float R  = g_scal[warp][2];
    float VA = g_scal[warp][3];
    float VB = g_scal[warp][4];
    float ab = attn_b[0];

    float xr[16];
    xr[0]=v0.x; xr[1]=v0.y; xr[2]=v0.z; xr[3]=v0.w;
    xr[4]=v1.x; xr[5]=v1.y; xr[6]=v1.z; xr[7]=v1.w;
    xr[8]=v2.x; xr[9]=v2.y; xr[10]=v2.z; xr[11]=v2.w;
    xr[12]=v3.x; xr[13]=v3.y; xr[14]=v3.z; xr[15]=v3.w;

    // ---- critical-path stats: only max/min needed before iteration 1 ----
    float Sl = 0.f, xmax = -1e30f, xmin = 1e30f;
    #pragma unroll
    for (int i = 0; i < 16; i++) {
        Sl += xr[i];
        xmax = fmaxf(xmax, xr[i]);
        xmin = fminf(xmin, xr[i]);
    }
    #pragma unroll
    for (int o = 16; o > 0; o >>= 1) {
        xmax = fmaxf(xmax, __shfl_xor_sync(0xffffffffu, xmax, o));
        xmin = fminf(xmin, __shfl_xor_sync(0xffffffffu, xmin, o));
    }

    // ---- L-step scalar softmax recursion: 4-way ILP, no live w[] array ----
    const float L2E = 1.4426950408889634f;
    float alpha = A0;
    float m = 0.f;
    #pragma unroll
    for (int it = 0; it < LL; it++) {
        float a2 = alpha * L2E;
        float M2 = (alpha >= 0.f) ? a2 * xmax : a2 * xmin;   // exact max logit
        float swa = 0.f, swb = 0.f, swc = 0.f, swd = 0.f;
        float sxa = 0.f, sxb = 0.f, sxc = 0.f, sxd = 0.f;
        #pragma unroll
        for (int i = 0; i < 4; i++) {
            float wa = ex2f(fmaf(a2, xr[4*i+0], -M2));
            float wb = ex2f(fmaf(a2, xr[4*i+1], -M2));
            float wc = ex2f(fmaf(a2, xr[4*i+2], -M2));
            float wd = ex2f(fmaf(a2, xr[4*i+3], -M2));
            swa += wa; sxa = fmaf(xr[4*i+0], wa, sxa);
            swb += wb; sxb = fmaf(xr[4*i+1], wb, sxb);
            swc += wc; sxc = fmaf(xr[4*i+2], wc, sxc);
            swd += wd; sxd = fmaf(xr[4*i+3], wd, sxd);
        }
        float sw  = (swa + swb) + (swc + swd);
        float sxw = (sxa + sxb) + (sxc + sxd);
        #pragma unroll
        for (int o = 16; o > 0; o >>= 1) {
            sw  += __shfl_xor_sync(0xffffffffu, sw,  o);
            sxw += __shfl_xor_sync(0xffffffffu, sxw, o);
        }
        m = __fdividef(sxw, sw);
        alpha = fmaf(m, P, R);
    }

    // ---- deferred sum butterfly (off the recursion path) ----
    float S = Sl;
    #pragma unroll
    for (int o = 16; o > 0; o >>= 1)
        S += __shfl_xor_sync(0xffffffffu, S, o);

    if (lane == 0) {
        s_ox[warp] = fmaf(m, VA, VB);                          // Qc contribution
        s_hc[warp] = fmaf(S - m, VA, (float)(FF - 1) * VB);    // (v_sum - Qc)
    }
    __syncthreads();   // single block sync

    float ox = ab, cc = ab;
    #pragma unroll
    for (int hh = 0; hh < HH; hh++) { ox += s_ox[hh]; cc += s_hc[hh]; }

    // ---- epilogue: one STG.128 per thread (values constant across f) ----
    // threads 0..127  -> out row b        (128 float4s)
    // threads 128..255-> out row BB*FF + b (128 float4s)
    float val = (t < 128) ? ox : cc;
    float4* dst = reinterpret_cast<float4*>(
        (t < 128) ? (out + b * FF) : (out + BB * FF + b * FF));
    dst[t & 127] = make_float4(val, val, val, val);
}

extern "C" void kernel_launch(void* const* d_in, const int* in_sizes, int n_in,
                              void* d_out, int out_size) {
    const float* features = (const float*)d_in[0];
    const float* emb_w    = (const float*)d_in[1];
    const float* emb_b    = (const float*)d_in[2];
    const float* q_w      = (const float*)d_in[3];
    const float* q_b      = (const float*)d_in[4];
    const float* k_w      = (const float*)d_in[5];
    // d_in[6] = k_b: cancels in softmax, unused
    const float* v_w      = (const float*)d_in[7];
    const float* v_b      = (const float*)d_in[8];
    const float* attn_w   = (const float*)d_in[9];
    const float* attn_b   = (const float*)d_in[10];
    float* out = (float*)d_out;

    precompute_kernel<<<48, 256>>>(emb_w, emb_b, q_w, q_b, k_w, v_w, v_b, attn_w);
    attn_kernel<<<BB, 256>>>(features, attn_b, out);
}

// round 11
// speedup vs baseline: 1.2316x; 1.2316x over previous
#include <cuda_runtime.h>
#include <math.h>

#define BB 64
#define FF 512
#define EE 256
#define HH 8
#define DD 32
#define LL 4

// Precomputed collapsed vectors (device globals: no allocation allowed)
__device__ float g_kw[EE];   // emb_w @ k_w
__device__ float g_vw[EE];   // emb_w @ v_w
__device__ float g_vb[EE];   // emb_b @ v_w + v_b
__device__ float g_qv[EE];   // emb_b @ q_w + q_b

__device__ __forceinline__ float ex2f(float x) {
    float y;
    asm("ex2.approx.ftz.f32 %0, %1;" : "=f"(y) : "f"(x));
    return y;
}

// ---------------------------------------------------------------------------
// Kernel A (r4-proven): 4 vector-matrix products, each 256-dot split across
// 8 warps (32 fully-unrolled strided loads each -> one DRAM round-trip).
// grid = 32 (4 matrices x 8 col-groups), 256 threads. No handshake: the
// kernel boundary synchronizes with kernel B.
// ---------------------------------------------------------------------------
__global__ void __launch_bounds__(256)
precompute_kernel(const float* __restrict__ emb_w,
                  const float* __restrict__ emb_b,
                  const float* __restrict__ q_w,
                  const float* __restrict__ q_b,
                  const float* __restrict__ k_w,
                  const float* __restrict__ v_w,
                  const float* __restrict__ v_b) {
    const int m     = blockIdx.x >> 3;          // 0:kw 1:vw 2:vb 3:qv
    const int grp   = blockIdx.x & 7;           // column group (32 cols)
    const int lane  = threadIdx.x & 31;
    const int chunk = threadIdx.x >> 5;         // row chunk == warp id
    const int col   = grp * 32 + lane;

    const float* vecsrc = (m <= 1) ? emb_w : emb_b;
    const float* mat    = (m == 0) ? k_w : (m == 3 ? q_w : v_w);

    float ev = vecsrc[chunk * 32 + lane];
    const float* mp = mat + (chunk * 32) * EE + col;

    float acc = 0.f;
    #pragma unroll
    for (int e = 0; e < 32; e++)
        acc = fmaf(__shfl_sync(0xffffffffu, ev, e), mp[e * EE], acc);

    __shared__ float s[8][32];
    s[chunk][lane] = acc;
    __syncthreads();

    if (threadIdx.x < 32) {
        float a = 0.f;
        #pragma unroll
        for (int r = 0; r < 8; r++) a += s[r][lane];
        if (m == 2) a += v_b[col];
        if (m == 3) a += q_b[col];
        float* dst = (m == 0) ? g_kw : (m == 1) ? g_vw : (m == 2) ? g_vb : g_qv;
        dst[col] = a;
    }
}

// ---------------------------------------------------------------------------
// Kernel B (r10-lean + in-warp scalar formation): grid = 64, 256 threads =
// 8 warps = 8 heads. No occupancy cap -> no spills. Warp h: features via
// 4x LDG.128 + 5 head-vector loads (all issued upfront), one combined
// 7-value butterfly (max/min + 5 dots), L=4 recursion with 4-way ILP,
// STG.128 epilogue.
// ---------------------------------------------------------------------------
__global__ void __launch_bounds__(256, 1)
attn_kernel(const float* __restrict__ features,
            const float* __restrict__ attn_w,
            const float* __restrict__ attn_b,
            float* __restrict__ out) {
    __shared__ float s_ox[HH], s_hc[HH];

    const int b    = blockIdx.x;
    const int t    = threadIdx.x;
    const int warp = t >> 5;
    const int lane = t & 31;

    // ---- all loads issued up front ----
    const float4* xb4 = reinterpret_cast<const float4*>(features + b * FF);
    float4 v0 = xb4[lane +  0];
    float4 v1 = xb4[lane + 32];
    float4 v2 = xb4[lane + 64];
    float4 v3 = xb4[lane + 96];

    const int hi = warp * DD + lane;
    float kw = g_kw[hi];
    float vw = g_vw[hi];
    float vb = g_vb[hi];
    float qv = g_qv[hi];
    float aw = attn_w[hi];
    float ab = attn_b[0];

    float xr[16];
    xr[0]=v0.x; xr[1]=v0.y; xr[2]=v0.z; xr[3]=v0.w;
    xr[4]=v1.x; xr[5]=v1.y; xr[6]=v1.z; xr[7]=v1.w;
    xr[8]=v2.x; xr[9]=v2.y; xr[10]=v2.z; xr[11]=v2.w;
    xr[12]=v3.x; xr[13]=v3.y; xr[14]=v3.z; xr[15]=v3.w;

    // ---- local stats ----
    float Sl = 0.f, xmax = -1e30f, xmin = 1e30f;
    #pragma unroll
    for (int i = 0; i < 16; i++) {
        Sl += xr[i];
        xmax = fmaxf(xmax, xr[i]);
        xmin = fminf(xmin, xr[i]);
    }

    // ---- head scalars (per-lane products) ----
    const float scale = 0.17677669529663687f;      // 1/sqrt(32)
    float A0 = qv * kw, P = vw * kw, R = vb * kw, VA = vw * aw, VB = vb * aw;

    // ---- one combined butterfly: max/min + 5 dot reductions ----
    #pragma unroll
    for (int o = 16; o > 0; o >>= 1) {
        xmax = fmaxf(xmax, __shfl_xor_sync(0xffffffffu, xmax, o));
        xmin = fminf(xmin, __shfl_xor_sync(0xffffffffu, xmin, o));
        A0  += __shfl_xor_sync(0xffffffffu, A0, o);
        P   += __shfl_xor_sync(0xffffffffu, P,  o);
        R   += __shfl_xor_sync(0xffffffffu, R,  o);
        VA  += __shfl_xor_sync(0xffffffffu, VA, o);
        VB  += __shfl_xor_sync(0xffffffffu, VB, o);
    }
    A0 *= scale; P *= scale; R *= scale;

    // ---- L-step scalar softmax recursion: 4-way ILP, no live w[] array ----
    const float L2E = 1.4426950408889634f;
    float alpha = A0;
    float m = 0.f;
    #pragma unroll
    for (int it = 0; it < LL; it++) {
        float a2 = alpha * L2E;
        float M2 = (alpha >= 0.f) ? a2 * xmax : a2 * xmin;   // exact max logit
        float swa = 0.f, swb = 0.f, swc = 0.f, swd = 0.f;
        float sxa = 0.f, sxb = 0.f, sxc = 0.f, sxd = 0.f;
        #pragma unroll
        for (int i = 0; i < 4; i++) {
            float wa = ex2f(fmaf(a2, xr[4*i+0], -M2));
            float wb = ex2f(fmaf(a2, xr[4*i+1], -M2));
            float wc = ex2f(fmaf(a2, xr[4*i+2], -M2));
            float wd = ex2f(fmaf(a2, xr[4*i+3], -M2));
            swa += wa; sxa = fmaf(xr[4*i+0], wa, sxa);
            swb += wb; sxb = fmaf(xr[4*i+1], wb, sxb);
            swc += wc; sxc = fmaf(xr[4*i+2], wc, sxc);
            swd += wd; sxd = fmaf(xr[4*i+3], wd, sxd);
        }
        float sw  = (swa + swb) + (swc + swd);
        float sxw = (sxa + sxb) + (sxc + sxd);
        #pragma unroll
        for (int o = 16; o > 0; o >>= 1) {
            sw  += __shfl_xor_sync(0xffffffffu, sw,  o);
            sxw += __shfl_xor_sync(0xffffffffu, sxw, o);
        }
        m = __fdividef(sxw, sw);
        alpha = fmaf(m, P, R);
    }

    // ---- deferred sum butterfly (off the recursion path) ----
    float S = Sl;
    #pragma unroll
    for (int o = 16; o > 0; o >>= 1)
        S += __shfl_xor_sync(0xffffffffu, S, o);

    if (lane == 0) {
        s_ox[warp] = fmaf(m, VA, VB);                          // Qc contribution
        s_hc[warp] = fmaf(S - m, VA, (float)(FF - 1) * VB);    // (v_sum - Qc)
    }
    __syncthreads();   // single block sync

    float ox = ab, cc = ab;
    #pragma unroll
    for (int hh = 0; hh < HH; hh++) { ox += s_ox[hh]; cc += s_hc[hh]; }

    // ---- epilogue: one STG.128 per thread (values constant across f) ----
    float val = (t < 128) ? ox : cc;
    float4* dst = reinterpret_cast<float4*>(
        (t < 128) ? (out + b * FF) : (out + BB * FF + b * FF));
    dst[t & 127] = make_float4(val, val, val, val);
}

extern "C" void kernel_launch(void* const* d_in, const int* in_sizes, int n_in,
                              void* d_out, int out_size) {
    const float* features = (const float*)d_in[0];
    const float* emb_w    = (const float*)d_in[1];
    const float* emb_b    = (const float*)d_in[2];
    const float* q_w      = (const float*)d_in[3];
    const float* q_b      = (const float*)d_in[4];
    const float* k_w      = (const float*)d_in[5];
    // d_in[6] = k_b: cancels in softmax, unused
    const float* v_w      = (const float*)d_in[7];
    const float* v_b      = (const float*)d_in[8];
    const float* attn_w   = (const float*)d_in[9];
    const float* attn_b   = (const float*)d_in[10];
    float* out = (float*)d_out;

    precompute_kernel<<<32, 256>>>(emb_w, emb_b, q_w, q_b, k_w, v_w, v_b);
    attn_kernel<<<BB, 256>>>(features, attn_w, attn_b, out);
}